// round 3
// baseline (speedup 1.0000x reference)
#include <cuda_runtime.h>
#include <math.h>
#include <stdint.h>

// Problem constants
#define NIMG   48            // 16 batches * 3 channels
#define NN     1024          // H == W
#define NROWS  (NIMG * NN)   // total 1-D FFTs per pass
#define OUT_HW 224
#define NTAPS  10
#define NBATCH 16

// ---------------- scratch (device globals; no allocations allowed) ----------
__device__ float2 d_scratch1[(size_t)NIMG * NN * NN];  // row-FFT out; later reused as spec (float)
__device__ float2 d_scratch2[(size_t)NIMG * NN * NN];  // transposed
__device__ float  d_tmpA[(size_t)NIMG * OUT_HW * NN];  // resize pass-A output
__device__ float2 d_tw[1024];                          // exp(-2*pi*i*k/1024)
__device__ float  d_wt[OUT_HW * NTAPS];                // jax antialiased triangle weights
__device__ int    d_j0[OUT_HW];                        // first tap index per output coord
__device__ unsigned int d_gmin[NBATCH];
__device__ unsigned int d_gmax[NBATCH];

// ---------------- complex helpers -------------------------------------------
__device__ __forceinline__ float2 cadd(float2 a, float2 b){ return make_float2(a.x+b.x, a.y+b.y); }
__device__ __forceinline__ float2 csub(float2 a, float2 b){ return make_float2(a.x-b.x, a.y-b.y); }
__device__ __forceinline__ float2 cmul(float2 a, float2 b){
    return make_float2(fmaf(a.x, b.x, -a.y*b.y), fmaf(a.x, b.y, a.y*b.x));
}

// padded shared index to break stride-128B bank conflicts
#define SIDX(i) ((i) + ((i) >> 5))

// reverse 4 base-4 digits of t in [0,256)
__device__ __forceinline__ int rev4_4(int t){
    return ((t & 3) << 6) | ((t & 12) << 2) | ((t >> 2) & 12) | ((t >> 6) & 3);
}

// ---------------- 1024-pt radix-4 DIT FFT core ------------------------------
// s: shared (padded) holding digit-reversed input. t: threadIdx.x in [0,256).
// On return r[q] = X[t + q*256] (natural frequency order).
__device__ __forceinline__ void fft1024_core(float2* s, int t, float2 r[4]){
    #pragma unroll
    for (int stage = 0; stage < 5; ++stage){
        const int m = 1 << (2*stage);
        const int j = t & (m - 1);
        const int base = ((t & ~(m - 1)) << 2) + j;   // blk*4m + j
        __syncthreads();
        float2 a = s[SIDX(base)];
        float2 b = s[SIDX(base +   m)];
        float2 c = s[SIDX(base + 2*m)];
        float2 d = s[SIDX(base + 3*m)];
        if (stage){
            int tw = j * (256 >> (2*stage));          // j * N/(4m)
            b = cmul(b, d_tw[tw]);
            c = cmul(c, d_tw[2*tw]);
            d = cmul(d, d_tw[3*tw]);
        }
        float2 t0 = cadd(a, c), t1 = csub(a, c);
        float2 t2 = cadd(b, d), t3 = csub(b, d);
        float2 t3p = make_float2(t3.y, -t3.x);        // -i * (b - d)
        float2 o0 = cadd(t0, t2), o1 = cadd(t1, t3p);
        float2 o2 = csub(t0, t2), o3 = csub(t1, t3p);
        if (stage < 4){
            s[SIDX(base)]       = o0;
            s[SIDX(base +   m)] = o1;
            s[SIDX(base + 2*m)] = o2;
            s[SIDX(base + 3*m)] = o3;
        } else {
            r[0] = o0; r[1] = o1; r[2] = o2; r[3] = o3;
        }
    }
}

// ---------------- init: twiddles, resize weights, min/max reset -------------
__global__ void init_kernel(){
    int t = blockIdx.x * blockDim.x + threadIdx.x;
    if (t < 1024){
        double ang = -2.0 * M_PI * (double)t / 1024.0;
        d_tw[t] = make_float2((float)cos(ang), (float)sin(ang));
    }
    int o = t - 1024;
    if (o >= 0 && o < OUT_HW){
        // jax.image.resize(method='bilinear', antialias=True), 1024 -> 224
        const double inv_scale = 1024.0 / 224.0;      // = 1/scale
        const double ks = inv_scale;                  // kernel_scale (antialias downsample)
        double c = ((double)o + 0.5) * inv_scale - 0.5;
        int j0 = (int)ceil(c - ks);
        if (j0 < 0) j0 = 0;
        double w[NTAPS]; double sum = 0.0;
        #pragma unroll
        for (int k = 0; k < NTAPS; ++k){
            int j = j0 + k;
            double ww = 0.0;
            if (j <= 1023){
                double x = fabs((double)j - c) / ks;
                ww = (x < 1.0) ? (1.0 - x) : 0.0;
            }
            w[k] = ww; sum += ww;
        }
        #pragma unroll
        for (int k = 0; k < NTAPS; ++k) d_wt[o*NTAPS + k] = (float)(w[k] / sum);
        d_j0[o] = j0;
    }
    int mi = t - (1024 + OUT_HW);
    if (mi >= 0 && mi < NBATCH){
        d_gmin[mi] = 0x7F800000u;   // +inf
        d_gmax[mi] = 0u;            // +0.0
    }
}

// ---------------- pass 1: row FFT (real input) ------------------------------
__global__ void __launch_bounds__(256) fft_rows_real(const float* __restrict__ x){
    __shared__ float2 s[1024 + 32];
    const size_t row = blockIdx.x;
    const float* xr = x + row * NN;
    const int t  = threadIdx.x;
    const int rt = rev4_4(t);
    #pragma unroll
    for (int q = 0; q < 4; ++q){
        float v = xr[t + q*256];
        s[SIDX(4*rt + q)] = make_float2(v, 0.f);      // digit-reversed placement
    }
    float2 r[4];
    fft1024_core(s, t, r);
    float2* o = d_scratch1 + row * NN;
    #pragma unroll
    for (int q = 0; q < 4; ++q) o[t + q*256] = r[q];
}

// ---------------- pass 2: per-image transpose -------------------------------
__global__ void __launch_bounds__(256) transpose_k(){
    __shared__ float2 tile[32][33];
    const size_t img = blockIdx.z;
    const int bx = blockIdx.x * 32, by = blockIdx.y * 32;
    const float2* I = d_scratch1 + (img << 20);
    float2*       O = d_scratch2 + (img << 20);
    #pragma unroll
    for (int i = threadIdx.y; i < 32; i += 8)
        tile[i][threadIdx.x] = I[(size_t)(by + i) * NN + bx + threadIdx.x];
    __syncthreads();
    #pragma unroll
    for (int i = threadIdx.y; i < 32; i += 8)
        O[(size_t)(bx + i) * NN + by + threadIdx.x] = tile[threadIdx.x][i];
}

// ---------------- pass 3: column FFT + log-mag + fftshift + min/max ---------
__global__ void __launch_bounds__(256) fft_cols(){
    __shared__ float2 s[1024 + 32];
    __shared__ float smin[8], smax[8];
    const size_t rowg = blockIdx.x;           // img*1024 + c (c = original column)
    const int img = (int)(rowg >> 10);
    const int c   = (int)(rowg & 1023);
    const float2* xr = d_scratch2 + rowg * NN;
    const int t  = threadIdx.x;
    const int rt = rev4_4(t);
    #pragma unroll
    for (int q = 0; q < 4; ++q) s[SIDX(4*rt + q)] = xr[t + q*256];
    float2 r[4];
    fft1024_core(s, t, r);

    const int sc = (c + 512) & 1023;
    float* sp = (float*)d_scratch1 + ((size_t)img << 20) + (size_t)sc * NN;  // specT[img][sc][sr]
    float lmin = 3.4e38f, lmax = 0.f;
    #pragma unroll
    for (int q = 0; q < 4; ++q){
        int rr = t + q*256;
        int sr = (rr + 512) & 1023;
        float m2 = fmaf(r[q].x, r[q].x, r[q].y * r[q].y);
        float v = log1pf(sqrtf(m2));
        sp[sr] = v;
        lmin = fminf(lmin, v);
        lmax = fmaxf(lmax, v);
    }
    // block reduce -> per-batch atomics (float bits order == uint order for v>=0)
    #pragma unroll
    for (int off = 16; off; off >>= 1){
        lmin = fminf(lmin, __shfl_xor_sync(0xFFFFFFFFu, lmin, off));
        lmax = fmaxf(lmax, __shfl_xor_sync(0xFFFFFFFFu, lmax, off));
    }
    const int wid = t >> 5, lane = t & 31;
    if (lane == 0){ smin[wid] = lmin; smax[wid] = lmax; }
    __syncthreads();
    if (t == 0){
        #pragma unroll
        for (int i = 1; i < 8; ++i){ lmin = fminf(lmin, smin[i]); lmax = fmaxf(lmax, smax[i]); }
        int b = img / 3;
        atomicMin(&d_gmin[b], __float_as_uint(lmin));
        atomicMax(&d_gmax[b], __float_as_uint(lmax));
    }
}

// ---------------- pass 4a: resize along spectral-x (sc dim) -----------------
__global__ void __launch_bounds__(256) resize_passA(){
    const int bid = blockIdx.x;
    const int img = bid / OUT_HW;
    const int ox  = bid % OUT_HW;
    const int j0  = d_j0[ox];
    float w[NTAPS];
    #pragma unroll
    for (int k = 0; k < NTAPS; ++k) w[k] = d_wt[ox*NTAPS + k];
    const float* S = (const float*)d_scratch1 + ((size_t)img << 20);
    float* T = d_tmpA + ((size_t)img * OUT_HW + ox) * NN;
    for (int sr = threadIdx.x; sr < NN; sr += 256){
        float acc = 0.f;
        #pragma unroll
        for (int k = 0; k < NTAPS; ++k){
            int j = min(j0 + k, 1023);
            acc = fmaf(w[k], S[(size_t)j * NN + sr], acc);
        }
        T[sr] = acc;
    }
}

// ---------------- pass 4b: resize along y + normalize -----------------------
__global__ void __launch_bounds__(256) resize_passB(float* __restrict__ out){
    __shared__ float sh[NN];
    const int bid = blockIdx.x;
    const int img = bid / OUT_HW;
    const int ox  = bid % OUT_HW;
    const float* T = d_tmpA + ((size_t)img * OUT_HW + ox) * NN;
    for (int i = threadIdx.x; i < NN; i += 256) sh[i] = T[i];
    __syncthreads();
    const int b = img / 3;
    const float mn = __uint_as_float(d_gmin[b]);
    const float mx = __uint_as_float(d_gmax[b]);
    const float inv = 1.f / (mx - mn + 1e-8f);
    for (int oy = threadIdx.x; oy < OUT_HW; oy += 256){
        const int j0 = d_j0[oy];
        float acc = 0.f;
        #pragma unroll
        for (int k = 0; k < NTAPS; ++k)
            acc = fmaf(d_wt[oy*NTAPS + k], sh[min(j0 + k, 1023)], acc);
        out[((size_t)img * OUT_HW + oy) * OUT_HW + ox] = (acc - mn) * inv;
    }
}

// ---------------- launch -----------------------------------------------------
extern "C" void kernel_launch(void* const* d_in, const int* in_sizes, int n_in,
                              void* d_out, int out_size){
    (void)in_sizes; (void)n_in; (void)out_size;
    const float* images = (const float*)d_in[0];
    float* out = (float*)d_out;

    init_kernel<<<6, 256>>>();
    fft_rows_real<<<NROWS, 256>>>(images);
    transpose_k<<<dim3(32, 32, NIMG), dim3(32, 8)>>>();
    fft_cols<<<NROWS, 256>>>();
    resize_passA<<<NIMG * OUT_HW, 256>>>();
    resize_passB<<<NIMG * OUT_HW, 256>>>(out);
}

// round 4
// speedup vs baseline: 1.7111x; 1.7111x over previous
#include <cuda_runtime.h>
#include <math.h>
#include <stdint.h>

// Problem constants
#define NIMG   48            // 16 batches * 3 channels
#define NN     1024          // H == W
#define OUT_HW 224
#define NTAPS  10
#define NBATCH 16
#define HCOLS  513           // Hermitian-unique columns (0..512)
#define HSTR   528           // padded row stride (float2) for pass-1 output; 528*8=4224B=33*128B

// ---------------- scratch (device globals; no allocations allowed) ----------
__device__ float2 d_scratch1[(size_t)NIMG * NN * NN];  // pass1 out [img][row][0..527]; later spec (float [img][1024][1024])
__device__ float2 d_scratch2[(size_t)NIMG * NN * NN];  // transposed [img][col 0..512][row]
__device__ float  d_tmpA[(size_t)NIMG * OUT_HW * NN];  // resize pass-A output
__device__ float2 d_tw[1024];                          // exp(-2*pi*i*k/1024)
__device__ float  d_wt[OUT_HW * NTAPS];                // jax antialiased triangle weights
__device__ int    d_j0[OUT_HW];                        // first tap index per output coord
__device__ unsigned int d_gmin[NBATCH];
__device__ unsigned int d_gmax[NBATCH];

// ---------------- complex helpers -------------------------------------------
__device__ __forceinline__ float2 cadd(float2 a, float2 b){ return make_float2(a.x+b.x, a.y+b.y); }
__device__ __forceinline__ float2 csub(float2 a, float2 b){ return make_float2(a.x-b.x, a.y-b.y); }
__device__ __forceinline__ float2 cmul(float2 a, float2 b){
    return make_float2(fmaf(a.x, b.x, -a.y*b.y), fmaf(a.x, b.y, a.y*b.x));
}

// padded shared index to break stride bank conflicts
#define SIDX(i) ((i) + ((i) >> 5))

// reverse 4 base-4 digits of t in [0,256)
__device__ __forceinline__ int rev4_4(int t){
    return ((t & 3) << 6) | ((t & 12) << 2) | ((t >> 2) & 12) | ((t >> 6) & 3);
}

// ---------------- 1024-pt radix-4 DIT FFT core ------------------------------
// s: shared (padded) holding digit-reversed input. t: threadIdx.x in [0,256).
// STORE_SMEM=true : final results stored back into s (natural order); caller must sync.
// STORE_SMEM=false: r[q] = X[t + q*256].
template<bool STORE_SMEM>
__device__ __forceinline__ void fft1024_core_t(float2* s, int t, float2 r[4]){
    #pragma unroll
    for (int stage = 0; stage < 5; ++stage){
        const int m = 1 << (2*stage);
        const int j = t & (m - 1);
        const int base = ((t & ~(m - 1)) << 2) + j;   // blk*4m + j
        __syncthreads();
        float2 a = s[SIDX(base)];
        float2 b = s[SIDX(base +   m)];
        float2 c = s[SIDX(base + 2*m)];
        float2 d = s[SIDX(base + 3*m)];
        if (stage){
            int tw = j * (256 >> (2*stage));          // j * N/(4m)
            b = cmul(b, d_tw[tw]);
            c = cmul(c, d_tw[2*tw]);
            d = cmul(d, d_tw[3*tw]);
        }
        float2 t0 = cadd(a, c), t1 = csub(a, c);
        float2 t2 = cadd(b, d), t3 = csub(b, d);
        float2 t3p = make_float2(t3.y, -t3.x);        // -i * (b - d)
        float2 o0 = cadd(t0, t2), o1 = cadd(t1, t3p);
        float2 o2 = csub(t0, t2), o3 = csub(t1, t3p);
        if (stage < 4 || STORE_SMEM){
            s[SIDX(base)]       = o0;
            s[SIDX(base +   m)] = o1;
            s[SIDX(base + 2*m)] = o2;
            s[SIDX(base + 3*m)] = o3;
        } else {
            r[0] = o0; r[1] = o1; r[2] = o2; r[3] = o3;
        }
    }
}

// ---------------- init: twiddles, resize weights, min/max reset -------------
__global__ void init_kernel(){
    int t = blockIdx.x * blockDim.x + threadIdx.x;
    if (t < 1024){
        double ang = -2.0 * M_PI * (double)t / 1024.0;
        d_tw[t] = make_float2((float)cos(ang), (float)sin(ang));
    }
    int o = t - 1024;
    if (o >= 0 && o < OUT_HW){
        // jax.image.resize(method='bilinear', antialias=True), 1024 -> 224
        const double inv_scale = 1024.0 / 224.0;
        const double ks = inv_scale;
        double c = ((double)o + 0.5) * inv_scale - 0.5;
        int j0 = (int)ceil(c - ks);
        if (j0 < 0) j0 = 0;
        double w[NTAPS]; double sum = 0.0;
        #pragma unroll
        for (int k = 0; k < NTAPS; ++k){
            int j = j0 + k;
            double ww = 0.0;
            if (j <= 1023){
                double x = fabs((double)j - c) / ks;
                ww = (x < 1.0) ? (1.0 - x) : 0.0;
            }
            w[k] = ww; sum += ww;
        }
        #pragma unroll
        for (int k = 0; k < NTAPS; ++k) d_wt[o*NTAPS + k] = (float)(w[k] / sum);
        d_j0[o] = j0;
    }
    int mi = t - (1024 + OUT_HW);
    if (mi >= 0 && mi < NBATCH){
        d_gmin[mi] = 0x7F800000u;   // +inf
        d_gmax[mi] = 0u;            // +0.0
    }
}

// ---------------- pass 1: paired-row real FFT (two rows per complex FFT) ----
// Block handles one pair of rows (2*pr, 2*pr+1) of one image.
// z = x1 + i*x2; X1[k] = (Z[k]+conj(Z[-k]))/2, X2[k] = -i(Z[k]-conj(Z[-k]))/2.
// Only k = 0..512 are stored (Hermitian symmetry makes the rest redundant).
__global__ void __launch_bounds__(256) fft_rows_pair(const float* __restrict__ x){
    __shared__ float2 s[1024 + 32];
    const int bid = blockIdx.x;
    const int img = bid >> 9;          // /512
    const int pr  = bid & 511;
    const float* x1 = x + ((size_t)img * NN + 2*pr) * NN;
    const float* x2 = x1 + NN;
    const int t  = threadIdx.x;
    const int rt = rev4_4(t);
    #pragma unroll
    for (int q = 0; q < 4; ++q){
        int n = t + q*256;
        s[SIDX(4*rt + q)] = make_float2(x1[n], x2[n]);  // digit-reversed placement
    }
    float2 dummy[4];
    fft1024_core_t<true>(s, t, dummy);
    __syncthreads();

    float2* o1 = d_scratch1 + ((size_t)img * NN + 2*pr) * HSTR;
    float2* o2 = o1 + HSTR;
    for (int k = t; k <= 512; k += 256){
        float2 Zk = s[SIDX(k)];
        float2 Zm = s[SIDX((1024 - k) & 1023)];
        o1[k] = make_float2(0.5f*(Zk.x + Zm.x), 0.5f*(Zk.y - Zm.y));
        o2[k] = make_float2(0.5f*(Zk.y + Zm.y), 0.5f*(Zm.x - Zk.x));
    }
}

// ---------------- pass 2: per-image transpose (1024 x 513 -> 513 x 1024) ----
__global__ void __launch_bounds__(256) transpose_half(){
    __shared__ float2 tile[32][33];
    const int img = blockIdx.z;
    const int bx = blockIdx.x * 32;    // column tile (0..512 valid)
    const int by = blockIdx.y * 32;    // row tile
    const float2* I = d_scratch1 + (size_t)img * NN * HSTR;
    float2*       O = d_scratch2 + (size_t)img * HCOLS * NN;
    const int col = bx + threadIdx.x;
    #pragma unroll
    for (int i = threadIdx.y; i < 32; i += 8)
        if (col < HCOLS)
            tile[i][threadIdx.x] = I[(size_t)(by + i) * HSTR + col];
    __syncthreads();
    const int orow_t = by + threadIdx.x;   // original row index
    #pragma unroll
    for (int i = threadIdx.y; i < 32; i += 8){
        int ocol = bx + i;                 // original column index
        if (ocol < HCOLS)
            O[(size_t)ocol * NN + orow_t] = tile[threadIdx.x][i];
    }
}

// ---------------- pass 3: column FFT (513 cols) + log-mag + shift + mirror --
__global__ void __launch_bounds__(256) fft_cols_half(){
    __shared__ float2 s[1024 + 32];
    __shared__ float smin[8], smax[8];
    const int bid = blockIdx.x;        // img*513 + c
    const int img = bid / HCOLS;
    const int c   = bid - img * HCOLS; // 0..512
    const float2* xr = d_scratch2 + ((size_t)img * HCOLS + c) * NN;
    const int t  = threadIdx.x;
    const int rt = rev4_4(t);
    #pragma unroll
    for (int q = 0; q < 4; ++q) s[SIDX(4*rt + q)] = xr[t + q*256];
    float2 r[4];
    fft1024_core_t<false>(s, t, r);

    // spec layout: [img][sc][sr] where sc = shifted col freq, sr = shifted row freq
    float* spB = (float*)d_scratch1 + ((size_t)img << 20);
    const int sc  = (c + 512) & 1023;
    const int sc2 = (1536 - c) & 1023;   // mirrored column ((1024-c)%1024 + 512)%1024
    float lmin = 3.4e38f, lmax = 0.f;
    #pragma unroll
    for (int q = 0; q < 4; ++q){
        int rr  = t + q*256;
        int sr  = (rr + 512) & 1023;
        int sr2 = (1536 - rr) & 1023;
        float m2 = fmaf(r[q].x, r[q].x, r[q].y * r[q].y);
        float v = log1pf(sqrtf(m2));
        spB[(size_t)sc  * NN + sr ] = v;
        spB[(size_t)sc2 * NN + sr2] = v;   // Hermitian mirror: |F[u,v]|=|F[-u,-v]|
        lmin = fminf(lmin, v);
        lmax = fmaxf(lmax, v);
    }
    // block reduce -> per-batch atomics (float bits order == uint order for v>=0)
    #pragma unroll
    for (int off = 16; off; off >>= 1){
        lmin = fminf(lmin, __shfl_xor_sync(0xFFFFFFFFu, lmin, off));
        lmax = fmaxf(lmax, __shfl_xor_sync(0xFFFFFFFFu, lmax, off));
    }
    const int wid = t >> 5, lane = t & 31;
    if (lane == 0){ smin[wid] = lmin; smax[wid] = lmax; }
    __syncthreads();
    if (t == 0){
        #pragma unroll
        for (int i = 1; i < 8; ++i){ lmin = fminf(lmin, smin[i]); lmax = fmaxf(lmax, smax[i]); }
        int b = img / 3;
        atomicMin(&d_gmin[b], __float_as_uint(lmin));
        atomicMax(&d_gmax[b], __float_as_uint(lmax));
    }
}

// ---------------- pass 4a: resize along spectral-x (sc dim) -----------------
__global__ void __launch_bounds__(256) resize_passA(){
    const int bid = blockIdx.x;
    const int img = bid / OUT_HW;
    const int ox  = bid % OUT_HW;
    const int j0  = d_j0[ox];
    float w[NTAPS];
    #pragma unroll
    for (int k = 0; k < NTAPS; ++k) w[k] = d_wt[ox*NTAPS + k];
    const float* S = (const float*)d_scratch1 + ((size_t)img << 20);
    float* T = d_tmpA + ((size_t)img * OUT_HW + ox) * NN;
    for (int sr = threadIdx.x; sr < NN; sr += 256){
        float acc = 0.f;
        #pragma unroll
        for (int k = 0; k < NTAPS; ++k){
            int j = min(j0 + k, 1023);
            acc = fmaf(w[k], S[(size_t)j * NN + sr], acc);
        }
        T[sr] = acc;
    }
}

// ---------------- pass 4b: resize along y + normalize -----------------------
__global__ void __launch_bounds__(256) resize_passB(float* __restrict__ out){
    __shared__ float sh[NN];
    const int bid = blockIdx.x;
    const int img = bid / OUT_HW;
    const int ox  = bid % OUT_HW;
    const float* T = d_tmpA + ((size_t)img * OUT_HW + ox) * NN;
    for (int i = threadIdx.x; i < NN; i += 256) sh[i] = T[i];
    __syncthreads();
    const int b = img / 3;
    const float mn = __uint_as_float(d_gmin[b]);
    const float mx = __uint_as_float(d_gmax[b]);
    const float inv = 1.f / (mx - mn + 1e-8f);
    for (int oy = threadIdx.x; oy < OUT_HW; oy += 256){
        const int j0 = d_j0[oy];
        float acc = 0.f;
        #pragma unroll
        for (int k = 0; k < NTAPS; ++k)
            acc = fmaf(d_wt[oy*NTAPS + k], sh[min(j0 + k, 1023)], acc);
        out[((size_t)img * OUT_HW + oy) * OUT_HW + ox] = (acc - mn) * inv;
    }
}

// ---------------- launch -----------------------------------------------------
extern "C" void kernel_launch(void* const* d_in, const int* in_sizes, int n_in,
                              void* d_out, int out_size){
    (void)in_sizes; (void)n_in; (void)out_size;
    const float* images = (const float*)d_in[0];
    float* out = (float*)d_out;

    init_kernel<<<6, 256>>>();
    fft_rows_pair<<<NIMG * 512, 256>>>(images);
    transpose_half<<<dim3(17, 32, NIMG), dim3(32, 8)>>>();
    fft_cols_half<<<NIMG * HCOLS, 256>>>();
    resize_passA<<<NIMG * OUT_HW, 256>>>();
    resize_passB<<<NIMG * OUT_HW, 256>>>(out);
}